// round 2
// baseline (speedup 1.0000x reference)
#include <cuda_runtime.h>
#include <cuda_bf16.h>
#include <cstdint>

// Problem constants
#define BATCH 32
#define SEQ   512
#define DIM   768
#define GV    512      // graph vocab per sample
#define GD    16
#define M_TOT (BATCH * SEQ)          // 16384
#define WP_COLS (DIM + 3 * GD)       // 816
#define LN_EPS 1e-12f

// ---------------------------------------------------------------------------
// Scratch (static device globals; no runtime allocation allowed)
// ---------------------------------------------------------------------------
__device__ __align__(16) float g_emb[(size_t)M_TOT * DIM];   // 48 MB: word+pos embeddings
__device__ __align__(16) float g_bias2[BATCH * DIM];         // per-(b,d) epilogue bias
__device__ float g_graphvec[BATCH * 3 * GD];                 // concat(g1,g2,g3)

// ---------------------------------------------------------------------------
// K0: emb[m,:] = word_emb[ids[m],:] + pos_emb[m % 512,:]
// one block per row, 192 threads x float4 (768 floats)
// ---------------------------------------------------------------------------
__global__ void emb_kernel(const int* __restrict__ ids,
                           const float* __restrict__ we,
                           const float* __restrict__ pe) {
    const int m = blockIdx.x;
    const int t = threadIdx.x;               // 0..191
    const int id = ids[m];
    const int s = m & (SEQ - 1);
    const float4* wr = (const float4*)(we + (size_t)id * DIM);
    const float4* pr = (const float4*)(pe + (size_t)s * DIM);
    float4 a = wr[t];
    float4 p = pr[t];
    float4 o = make_float4(a.x + p.x, a.y + p.y, a.z + p.z, a.w + p.w);
    ((float4*)(g_emb + (size_t)m * DIM))[t] = o;
}

// ---------------------------------------------------------------------------
// K1: per (b, branch):
//   c[h]   = sum_g adj[b,g,h]                       (colsum — mean-pool commuted)
//   g[d]   = (1/G) * sum_h c[h] * word_emb[gv[b,h], d]
//   out[j] = relu( sum_d g[d] * W[j,d] + bias[j] ), j<16
// grid (32, 3), 256 threads
// ---------------------------------------------------------------------------
__global__ void vgcn_kernel(const float* __restrict__ adj_c, const int* __restrict__ gv_c,
                            const float* __restrict__ W_c,   const float* __restrict__ b_c,
                            const float* __restrict__ adj_h, const int* __restrict__ gv_h,
                            const float* __restrict__ W_h,   const float* __restrict__ b_h,
                            const float* __restrict__ adj_i, const int* __restrict__ gv_i,
                            const float* __restrict__ W_i,   const float* __restrict__ b_i,
                            const float* __restrict__ we) {
    __shared__ float csum[GV];
    __shared__ float gsh[DIM];
    __shared__ int   gvsh[GV];

    const int b  = blockIdx.x;
    const int br = blockIdx.y;
    const int tid = threadIdx.x;

    const float* adj; const int* gv; const float* W; const float* bv;
    if (br == 0)      { adj = adj_c; gv = gv_c; W = W_c; bv = b_c; }
    else if (br == 1) { adj = adj_h; gv = gv_h; W = W_h; bv = b_h; }
    else              { adj = adj_i; gv = gv_i; W = W_i; bv = b_i; }

    // --- phase 1: column sums of adj[b] (sum over g for each h) ---
    const float* adjb = adj + (size_t)b * GV * GV;
    const int h0 = tid, h1 = tid + 256;
    float a0 = 0.f, a1 = 0.f;
#pragma unroll 4
    for (int g = 0; g < GV; ++g) {
        const float* r = adjb + (size_t)g * GV;
        a0 += r[h0];
        a1 += r[h1];
    }
    csum[h0] = a0; csum[h1] = a1;
    gvsh[h0] = gv[b * GV + h0];
    gvsh[h1] = gv[b * GV + h1];
    __syncthreads();

    // --- phase 2: weighted sum of gathered word embeddings ---
    const int d0 = tid, d1 = tid + 256, d2 = tid + 512;
    float s0 = 0.f, s1 = 0.f, s2 = 0.f;
#pragma unroll 4
    for (int h = 0; h < GV; ++h) {
        const float w = csum[h];
        const float* er = we + (size_t)gvsh[h] * DIM;
        s0 += w * er[d0];
        s1 += w * er[d1];
        s2 += w * er[d2];
    }
    const float inv = 1.f / (float)GV;
    gsh[d0] = s0 * inv;
    gsh[d1] = s1 * inv;
    gsh[d2] = s2 * inv;
    __syncthreads();

    // --- phase 3: tiny FC (16 outputs) + relu; warp w does j = w, w+8 ---
    const int warp = tid >> 5, lane = tid & 31;
#pragma unroll
    for (int jj = 0; jj < 2; ++jj) {
        const int j = warp + jj * 8;
        float s = 0.f;
        for (int d = lane; d < DIM; d += 32) s += gsh[d] * W[j * DIM + d];
#pragma unroll
        for (int o = 16; o > 0; o >>= 1) s += __shfl_xor_sync(0xffffffffu, s, o);
        if (lane == 0)
            g_graphvec[b * 48 + br * GD + j] = fmaxf(s + bv[j], 0.f);
    }
}

// ---------------------------------------------------------------------------
// K2: bias2[b,d] = b_proj[d] + sum_{j<48} graphvec[b,j] * W_proj[d, 768+j]
// grid 32, 256 threads
// ---------------------------------------------------------------------------
__global__ void bias2_kernel(const float* __restrict__ Wp,
                             const float* __restrict__ bp) {
    __shared__ float gvs[48];
    const int b = blockIdx.x;
    const int tid = threadIdx.x;
    if (tid < 48) gvs[tid] = g_graphvec[b * 48 + tid];
    __syncthreads();
    for (int d = tid; d < DIM; d += 256) {
        float s = bp[d];
        const float* wr = Wp + (size_t)d * WP_COLS + DIM;
#pragma unroll
        for (int j = 0; j < 48; ++j) s += gvs[j] * wr[j];
        g_bias2[b * DIM + d] = s;
    }
}

// ---------------------------------------------------------------------------
// K3: Y[m,n] = sum_k emb[m,k] * W_proj[n,k] + bias2[m/512, n]
// double-buffered 128x128x8 fp32 SMEM GEMM, 256 threads, 8x8 per thread
// M=16384, N=768, K=768 (exact tiles, no bounds checks)
// ---------------------------------------------------------------------------
__global__ __launch_bounds__(256, 2)
void proj_gemm_kernel(const float* __restrict__ Wp,
                      float* __restrict__ Y) {
    __shared__ float As[2][8][128];
    __shared__ float Bs[2][8][128];
    const int tid = threadIdx.x;
    const int m0 = blockIdx.y * 128;
    const int n0 = blockIdx.x * 128;
    const int lr = tid >> 1;              // 0..127 tile row
    const int lk = (tid & 1) << 2;        // 0 or 4
    const float* Aptr = g_emb + (size_t)(m0 + lr) * DIM + lk;
    const float* Bptr = Wp + (size_t)(n0 + lr) * WP_COLS + lk;
    const int ty = tid >> 4;              // 0..15
    const int tx = tid & 15;              // 0..15

    float acc[8][8];
#pragma unroll
    for (int i = 0; i < 8; ++i)
#pragma unroll
        for (int j = 0; j < 8; ++j) acc[i][j] = 0.f;

    float4 a4 = *(const float4*)Aptr;
    float4 b4 = *(const float4*)Bptr;
    As[0][lk + 0][lr] = a4.x; As[0][lk + 1][lr] = a4.y;
    As[0][lk + 2][lr] = a4.z; As[0][lk + 3][lr] = a4.w;
    Bs[0][lk + 0][lr] = b4.x; Bs[0][lk + 1][lr] = b4.y;
    Bs[0][lk + 2][lr] = b4.z; Bs[0][lk + 3][lr] = b4.w;
    __syncthreads();

    int buf = 0;
    const int NKB = DIM / 8;   // 96
    for (int kb = 0; kb < NKB; ++kb) {
        if (kb < NKB - 1) {
            a4 = *(const float4*)(Aptr + (kb + 1) * 8);
            b4 = *(const float4*)(Bptr + (kb + 1) * 8);
        }
#pragma unroll
        for (int k = 0; k < 8; ++k) {
            float ar[8], br[8];
            *(float4*)&ar[0] = *(const float4*)&As[buf][k][ty * 8];
            *(float4*)&ar[4] = *(const float4*)&As[buf][k][ty * 8 + 4];
            *(float4*)&br[0] = *(const float4*)&Bs[buf][k][tx * 8];
            *(float4*)&br[4] = *(const float4*)&Bs[buf][k][tx * 8 + 4];
#pragma unroll
            for (int i = 0; i < 8; ++i)
#pragma unroll
                for (int j = 0; j < 8; ++j)
                    acc[i][j] += ar[i] * br[j];
        }
        if (kb < NKB - 1) {
            const int nb = buf ^ 1;
            As[nb][lk + 0][lr] = a4.x; As[nb][lk + 1][lr] = a4.y;
            As[nb][lk + 2][lr] = a4.z; As[nb][lk + 3][lr] = a4.w;
            Bs[nb][lk + 0][lr] = b4.x; Bs[nb][lk + 1][lr] = b4.y;
            Bs[nb][lk + 2][lr] = b4.z; Bs[nb][lk + 3][lr] = b4.w;
            __syncthreads();
            buf = nb;
        }
    }

    // epilogue: add per-(batch, n) bias; BM=128 divides 512, so one batch/block
    const int bidx = m0 >> 9;
    const float* bz = g_bias2 + bidx * DIM + n0 + tx * 8;
    const float4 bz0 = *(const float4*)bz;
    const float4 bz1 = *(const float4*)(bz + 4);
#pragma unroll
    for (int i = 0; i < 8; ++i) {
        float* yr = Y + (size_t)(m0 + ty * 8 + i) * DIM + n0 + tx * 8;
        float4 o0 = make_float4(acc[i][0] + bz0.x, acc[i][1] + bz0.y,
                                acc[i][2] + bz0.z, acc[i][3] + bz0.w);
        float4 o1 = make_float4(acc[i][4] + bz1.x, acc[i][5] + bz1.y,
                                acc[i][6] + bz1.z, acc[i][7] + bz1.w);
        *(float4*)yr = o0;
        *(float4*)(yr + 4) = o1;
    }
}

// ---------------------------------------------------------------------------
// K4: in-place LayerNorm over last dim (768), one block per row, 256 threads
// ---------------------------------------------------------------------------
__global__ void ln_kernel(float* __restrict__ Y,
                          const float* __restrict__ gamma,
                          const float* __restrict__ beta) {
    __shared__ float red[8];
    __shared__ float bc0, bc1;
    const int row = blockIdx.x;
    const int tid = threadIdx.x;
    float* yr = Y + (size_t)row * DIM;
    const float v0 = yr[tid], v1 = yr[tid + 256], v2 = yr[tid + 512];

    float s = v0 + v1 + v2;
#pragma unroll
    for (int o = 16; o > 0; o >>= 1) s += __shfl_xor_sync(0xffffffffu, s, o);
    if ((tid & 31) == 0) red[tid >> 5] = s;
    __syncthreads();
    if (tid < 8) {
        float t = red[tid];
#pragma unroll
        for (int o = 4; o > 0; o >>= 1) t += __shfl_xor_sync(0xffu, t, o);
        if (tid == 0) bc0 = t;
    }
    __syncthreads();
    const float mu = bc0 * (1.f / (float)DIM);
    const float d0 = v0 - mu, d1 = v1 - mu, d2 = v2 - mu;

    float q = d0 * d0 + d1 * d1 + d2 * d2;
#pragma unroll
    for (int o = 16; o > 0; o >>= 1) q += __shfl_xor_sync(0xffffffffu, q, o);
    __syncthreads();                    // protect red[] from WAR
    if ((tid & 31) == 0) red[tid >> 5] = q;
    __syncthreads();
    if (tid < 8) {
        float t = red[tid];
#pragma unroll
        for (int o = 4; o > 0; o >>= 1) t += __shfl_xor_sync(0xffu, t, o);
        if (tid == 0) bc1 = t;
    }
    __syncthreads();
    const float rstd = rsqrtf(bc1 * (1.f / (float)DIM) + LN_EPS);

    yr[tid]       = d0 * rstd * gamma[tid]       + beta[tid];
    yr[tid + 256] = d1 * rstd * gamma[tid + 256] + beta[tid + 256];
    yr[tid + 512] = d2 * rstd * gamma[tid + 512] + beta[tid + 512];
}

// ---------------------------------------------------------------------------
// Launch
// ---------------------------------------------------------------------------
extern "C" void kernel_launch(void* const* d_in, const int* in_sizes, int n_in,
                              void* d_out, int out_size) {
    const int*   ids   = (const int*)  d_in[0];
    const float* adj_c = (const float*)d_in[1];
    const int*   gv_c  = (const int*)  d_in[2];
    const float* adj_h = (const float*)d_in[3];
    const int*   gv_h  = (const int*)  d_in[4];
    const float* adj_i = (const float*)d_in[5];
    const int*   gv_i  = (const int*)  d_in[6];
    const float* we    = (const float*)d_in[7];
    const float* pe    = (const float*)d_in[8];
    const float* W_c   = (const float*)d_in[9];
    const float* b_c   = (const float*)d_in[10];
    const float* W_h   = (const float*)d_in[11];
    const float* b_h   = (const float*)d_in[12];
    const float* W_i   = (const float*)d_in[13];
    const float* b_i   = (const float*)d_in[14];
    const float* Wp    = (const float*)d_in[15];
    const float* bp    = (const float*)d_in[16];
    const float* gam   = (const float*)d_in[17];
    const float* bet   = (const float*)d_in[18];
    float* Y = (float*)d_out;

    emb_kernel<<<M_TOT, 192>>>(ids, we, pe);
    vgcn_kernel<<<dim3(BATCH, 3), 256>>>(adj_c, gv_c, W_c, b_c,
                                         adj_h, gv_h, W_h, b_h,
                                         adj_i, gv_i, W_i, b_i, we);
    bias2_kernel<<<BATCH, 256>>>(Wp, bp);
    proj_gemm_kernel<<<dim3(DIM / 128, M_TOT / 128), 256>>>(Wp, Y);
    ln_kernel<<<M_TOT, 256>>>(Y, gam, bet);
}

// round 9
// speedup vs baseline: 2.0214x; 2.0214x over previous
#include <cuda_runtime.h>
#include <cuda_bf16.h>
#include <cstdint>

#define BATCH 32
#define SEQ   512
#define DIM   768
#define GV    512
#define GD    16
#define M_TOT (BATCH * SEQ)          // 16384
#define WP_COLS (DIM + 3 * GD)       // 816
#define LN_EPS 1e-12f

// GEMM: C[16384,768] = A'[16384,2304] * B'[768,2304]^T  (bf16x3 split, mma.sync)
#define NKC 72                       // 2304 / 32 k-chunks
#define STAGE_BYTES 20480            // A 128x40 bf16 (10240) + B 128x40 bf16
#define SMEM_DYN (4 * STAGE_BYTES)   // 81920

// ---------------------------------------------------------------------------
// Device globals (scratch; no runtime allocation allowed)
// ---------------------------------------------------------------------------
__device__ __align__(16) __nv_bfloat16 g_emb_hi[(size_t)M_TOT * DIM];
__device__ __align__(16) __nv_bfloat16 g_emb_lo[(size_t)M_TOT * DIM];
__device__ __align__(16) __nv_bfloat16 g_wp_hi[DIM * DIM];
__device__ __align__(16) __nv_bfloat16 g_wp_lo[DIM * DIM];
__device__ __align__(16) float g_bias2[BATCH * DIM];
__device__ float g_graphvec[BATCH * 3 * GD];
__device__ float g_csum_part[BATCH * 3 * 8 * GV];
__device__ float g_pool[BATCH * 3 * 4 * DIM];

// ---------------------------------------------------------------------------
// PTX helpers (all base-sm_103 legal: cp.async, ldmatrix, mma.sync)
// ---------------------------------------------------------------------------
__device__ __forceinline__ uint32_t smem_u32(const void* p) {
    uint32_t a;
    asm("{ .reg .u64 t; cvta.to.shared.u64 t, %1; cvt.u32.u64 %0, t; }" : "=r"(a) : "l"(p));
    return a;
}
__device__ __forceinline__ void cp16(uint32_t dst, const void* src) {
    asm volatile("cp.async.cg.shared.global [%0], [%1], 16;" :: "r"(dst), "l"(src));
}
__device__ __forceinline__ void cp_commit() {
    asm volatile("cp.async.commit_group;" ::: "memory");
}
__device__ __forceinline__ void cp_wait2() {
    asm volatile("cp.async.wait_group 2;" ::: "memory");
}
__device__ __forceinline__ void ldm_x4(uint32_t& r0, uint32_t& r1, uint32_t& r2,
                                       uint32_t& r3, uint32_t addr) {
    asm volatile("ldmatrix.sync.aligned.m8n8.x4.shared.b16 {%0,%1,%2,%3}, [%4];"
                 : "=r"(r0), "=r"(r1), "=r"(r2), "=r"(r3) : "r"(addr));
}
__device__ __forceinline__ void mma16816(float* d, const uint32_t* a,
                                         uint32_t b0, uint32_t b1) {
    asm volatile(
        "mma.sync.aligned.m16n8k16.row.col.f32.bf16.bf16.f32 "
        "{%0,%1,%2,%3}, {%4,%5,%6,%7}, {%8,%9}, {%0,%1,%2,%3};"
        : "+f"(d[0]), "+f"(d[1]), "+f"(d[2]), "+f"(d[3])
        : "r"(a[0]), "r"(a[1]), "r"(a[2]), "r"(a[3]), "r"(b0), "r"(b1));
}

// stage load: chunk c -> buffer (c&3).  A/B tiles 128 rows x 32 bf16, row pad to 80B
__device__ __forceinline__ void stage_load(uint32_t sb, int tid, int m0, int n0, int c) {
    const int st = c & 3;
    const int seg = c / 24;
    const int kk = (c - seg * 24) * 32;
    const char* As = (const char*)((seg == 1 ? g_emb_lo : g_emb_hi)
                                   + (size_t)m0 * DIM + kk);
    const char* Bs = (const char*)((seg == 2 ? g_wp_lo : g_wp_hi)
                                   + (size_t)n0 * DIM + kk);
    const uint32_t sa = sb + st * STAGE_BYTES;
    const uint32_t sbb = sa + 10240;
#pragma unroll
    for (int i = 0; i < 2; ++i) {
        const int ch = tid + i * 256;          // 0..511
        const int row = ch >> 2, c4 = ch & 3;  // row 0..127, 16B chunk 0..3
        cp16(sa + row * 80 + c4 * 16, As + (size_t)row * (DIM * 2) + c4 * 16);
        cp16(sbb + row * 80 + c4 * 16, Bs + (size_t)row * (DIM * 2) + c4 * 16);
    }
}

// ---------------------------------------------------------------------------
// K0: gather + pos add, split to bf16 hi/lo
// ---------------------------------------------------------------------------
__global__ void emb_kernel(const int* __restrict__ ids,
                           const float* __restrict__ we,
                           const float* __restrict__ pe) {
    const int m = blockIdx.x;
    const int t = threadIdx.x;               // 0..191
    const int id = ids[m];
    const int s = m & (SEQ - 1);
    float4 a = ((const float4*)(we + (size_t)id * DIM))[t];
    float4 p = ((const float4*)(pe + (size_t)s * DIM))[t];
    float v[4] = {a.x + p.x, a.y + p.y, a.z + p.z, a.w + p.w};
    __nv_bfloat16 h[4], l[4];
#pragma unroll
    for (int e = 0; e < 4; ++e) {
        h[e] = __float2bfloat16(v[e]);
        l[e] = __float2bfloat16(v[e] - __bfloat162float(h[e]));
    }
    const size_t off = (size_t)m * DIM + t * 4;
    *(uint2*)(g_emb_hi + off) = *(uint2*)h;
    *(uint2*)(g_emb_lo + off) = *(uint2*)l;
}

// ---------------------------------------------------------------------------
// K0b: W_proj[:, :768] -> bf16 hi/lo
// ---------------------------------------------------------------------------
__global__ void wpconv_kernel(const float* __restrict__ Wp) {
    const int n = blockIdx.x;
    const int tid = threadIdx.x;
#pragma unroll
    for (int i = 0; i < 3; ++i) {
        const int k = tid + i * 256;
        const float v = Wp[(size_t)n * WP_COLS + k];
        const __nv_bfloat16 h = __float2bfloat16(v);
        g_wp_hi[n * DIM + k] = h;
        g_wp_lo[n * DIM + k] = __float2bfloat16(v - __bfloat162float(h));
    }
}

// ---------------------------------------------------------------------------
// K1a: colsum partials over g-slices
// ---------------------------------------------------------------------------
__global__ void colsum_kernel(const float* __restrict__ adj_c,
                              const float* __restrict__ adj_h,
                              const float* __restrict__ adj_i) {
    const int b = blockIdx.x, br = blockIdx.y, z = blockIdx.z;
    const int tid = threadIdx.x;             // 0..511 = h
    const float* adj = (br == 0) ? adj_c : (br == 1) ? adj_h : adj_i;
    const float* adjb = adj + (size_t)b * GV * GV + (size_t)(z * 64) * GV;
    float a = 0.f;
#pragma unroll 4
    for (int g = 0; g < 64; ++g) a += adjb[(size_t)g * GV + tid];
    g_csum_part[(((b * 3) + br) * 8 + z) * GV + tid] = a;
}

// ---------------------------------------------------------------------------
// K1b: pool partials over h-slices
// ---------------------------------------------------------------------------
__global__ void pool_kernel(const int* __restrict__ gv_c,
                            const int* __restrict__ gv_h,
                            const int* __restrict__ gv_i,
                            const float* __restrict__ we) {
    __shared__ float cs[128];
    __shared__ int   gvs[128];
    const int b = blockIdx.x, br = blockIdx.y, w = blockIdx.z;
    const int tid = threadIdx.x;
    const int bb = b * 3 + br;
    const int hb = w * 128;
    const int* gv = (br == 0) ? gv_c : (br == 1) ? gv_h : gv_i;

    if (tid < 128) {
        float s = 0.f;
#pragma unroll
        for (int z = 0; z < 8; ++z)
            s += g_csum_part[(bb * 8 + z) * GV + hb + tid];
        cs[tid] = s;
        gvs[tid] = gv[b * GV + hb + tid];
    }
    __syncthreads();

    const int d0 = tid, d1 = tid + 256, d2 = tid + 512;
    float s0 = 0.f, s1 = 0.f, s2 = 0.f;
#pragma unroll 4
    for (int h = 0; h < 128; ++h) {
        const float wt = cs[h];
        const float* er = we + (size_t)gvs[h] * DIM;
        s0 += wt * er[d0];
        s1 += wt * er[d1];
        s2 += wt * er[d2];
    }
    float* out = g_pool + (size_t)(bb * 4 + w) * DIM;
    out[d0] = s0; out[d1] = s1; out[d2] = s2;
}

// ---------------------------------------------------------------------------
// K1c: reduce pool partials + 16-wide FC + relu
// ---------------------------------------------------------------------------
__global__ void fc_kernel(const float* __restrict__ W_c, const float* __restrict__ b_c,
                          const float* __restrict__ W_h, const float* __restrict__ b_h,
                          const float* __restrict__ W_i, const float* __restrict__ b_i) {
    __shared__ float gsh[DIM];
    const int b = blockIdx.x, br = blockIdx.y;
    const int tid = threadIdx.x;
    const int bb = b * 3 + br;
    const float* W; const float* bv;
    if (br == 0)      { W = W_c; bv = b_c; }
    else if (br == 1) { W = W_h; bv = b_h; }
    else              { W = W_i; bv = b_i; }

    const float* pool = g_pool + (size_t)bb * 4 * DIM;
#pragma unroll
    for (int i = 0; i < 3; ++i) {
        const int d = tid + i * 256;
        gsh[d] = (pool[d] + pool[DIM + d] + pool[2 * DIM + d] + pool[3 * DIM + d])
                 * (1.f / (float)GV);
    }
    __syncthreads();

    const int warp = tid >> 5, lane = tid & 31;
#pragma unroll
    for (int jj = 0; jj < 2; ++jj) {
        const int j = warp + jj * 8;
        float s = 0.f;
        for (int d = lane; d < DIM; d += 32) s += gsh[d] * W[j * DIM + d];
#pragma unroll
        for (int o = 16; o > 0; o >>= 1) s += __shfl_xor_sync(0xffffffffu, s, o);
        if (lane == 0)
            g_graphvec[b * 48 + br * GD + j] = fmaxf(s + bv[j], 0.f);
    }
}

// ---------------------------------------------------------------------------
// K2: bias2[b,d] = b_proj[d] + sum_{j<48} graphvec[b,j] * W_proj[d, 768+j]
// ---------------------------------------------------------------------------
__global__ void bias2_kernel(const float* __restrict__ Wp,
                             const float* __restrict__ bp) {
    __shared__ float gvs[48];
    const int b = blockIdx.x;
    const int tid = threadIdx.x;
    if (tid < 48) gvs[tid] = g_graphvec[b * 48 + tid];
    __syncthreads();
    for (int d = tid; d < DIM; d += 256) {
        float s = bp[d];
        const float* wr = Wp + (size_t)d * WP_COLS + DIM;
#pragma unroll
        for (int j = 0; j < 48; ++j) s += gvs[j] * wr[j];
        g_bias2[b * DIM + d] = s;
    }
}

// ---------------------------------------------------------------------------
// K3: bf16x3 GEMM via mma.sync (HMMA).  CTA 128x128, warp 64x32, 4-stage cp.async
// ---------------------------------------------------------------------------
__global__ __launch_bounds__(256, 2)
void proj_gemm_mma(float* __restrict__ Y) {
    extern __shared__ char smem[];
    const uint32_t sb = smem_u32(smem);
    const int tid = threadIdx.x;
    const int wid = tid >> 5, lane = tid & 31;
    const int m0 = blockIdx.y * 128;
    const int n0 = blockIdx.x * 128;
    const int wm = wid & 1;          // M half (64 rows)
    const int wn = wid >> 1;         // N group (32 cols)

    float acc[4][4][4];
#pragma unroll
    for (int i = 0; i < 4; ++i)
#pragma unroll
        for (int j = 0; j < 4; ++j)
#pragma unroll
            for (int e = 0; e < 4; ++e) acc[i][j][e] = 0.f;

    // prologue: prefetch 3 stages
    stage_load(sb, tid, m0, n0, 0); cp_commit();
    stage_load(sb, tid, m0, n0, 1); cp_commit();
    stage_load(sb, tid, m0, n0, 2); cp_commit();

    const int lrow = lane & 15, lhal = (lane >> 4) << 4;  // ldmatrix addr pieces

    for (int c = 0; c < NKC; ++c) {
        cp_wait2();
        __syncthreads();
        const uint32_t sa = sb + (c & 3) * STAGE_BYTES;
        const uint32_t sbb = sa + 10240;
#pragma unroll
        for (int ks = 0; ks < 2; ++ks) {
            uint32_t a[4][4];
            uint32_t bfr[4][2];
#pragma unroll
            for (int i = 0; i < 4; ++i)
                ldm_x4(a[i][0], a[i][1], a[i][2], a[i][3],
                       sa + (uint32_t)(wm * 64 + i * 16 + lrow) * 80 + ks * 32 + lhal);
#pragma unroll
            for (int j = 0; j < 2; ++j) {
                uint32_t r0, r1, r2, r3;
                ldm_x4(r0, r1, r2, r3,
                       sbb + (uint32_t)(wn * 32 + j * 16 + lrow) * 80 + ks * 32 + lhal);
                bfr[j * 2 + 0][0] = r0; bfr[j * 2 + 1][0] = r1;
                bfr[j * 2 + 0][1] = r2; bfr[j * 2 + 1][1] = r3;
            }
#pragma unroll
            for (int i = 0; i < 4; ++i)
#pragma unroll
                for (int nt = 0; nt < 4; ++nt)
                    mma16816(acc[i][nt], a[i], bfr[nt][0], bfr[nt][1]);
        }
        __syncthreads();
        if (c + 3 < NKC) stage_load(sb, tid, m0, n0, c + 3);
        cp_commit();                       // empty group on tail keeps wait uniform
    }

    // epilogue: direct stores + bias2
    const int bidx = m0 >> 9;
    const float* bz = g_bias2 + bidx * DIM + n0 + wn * 32;
    float* ybase = Y + (size_t)(m0 + wm * 64) * DIM + n0 + wn * 32;
#pragma unroll
    for (int nt = 0; nt < 4; ++nt) {
        const int n = nt * 8 + (lane & 3) * 2;
        const float2 bv = *(const float2*)(bz + n);
#pragma unroll
        for (int i = 0; i < 4; ++i) {
            const int r = i * 16 + (lane >> 2);
            float2 o0 = make_float2(acc[i][nt][0] + bv.x, acc[i][nt][1] + bv.y);
            float2 o1 = make_float2(acc[i][nt][2] + bv.x, acc[i][nt][3] + bv.y);
            *(float2*)(ybase + (size_t)r * DIM + n) = o0;
            *(float2*)(ybase + (size_t)(r + 8) * DIM + n) = o1;
        }
    }
}

// ---------------------------------------------------------------------------
// K4: in-place LayerNorm over last dim (768)
// ---------------------------------------------------------------------------
__global__ void ln_kernel(float* __restrict__ Y,
                          const float* __restrict__ gamma,
                          const float* __restrict__ beta) {
    __shared__ float red[8];
    __shared__ float bc0, bc1;
    const int row = blockIdx.x;
    const int tid = threadIdx.x;
    float* yr = Y + (size_t)row * DIM;
    const float v0 = yr[tid], v1 = yr[tid + 256], v2 = yr[tid + 512];

    float s = v0 + v1 + v2;
#pragma unroll
    for (int o = 16; o > 0; o >>= 1) s += __shfl_xor_sync(0xffffffffu, s, o);
    if ((tid & 31) == 0) red[tid >> 5] = s;
    __syncthreads();
    if (tid < 8) {
        float t = red[tid];
#pragma unroll
        for (int o = 4; o > 0; o >>= 1) t += __shfl_xor_sync(0xffu, t, o);
        if (tid == 0) bc0 = t;
    }
    __syncthreads();
    const float mu = bc0 * (1.f / (float)DIM);
    const float d0 = v0 - mu, d1 = v1 - mu, d2 = v2 - mu;

    float q = d0 * d0 + d1 * d1 + d2 * d2;
#pragma unroll
    for (int o = 16; o > 0; o >>= 1) q += __shfl_xor_sync(0xffffffffu, q, o);
    __syncthreads();
    if ((tid & 31) == 0) red[tid >> 5] = q;
    __syncthreads();
    if (tid < 8) {
        float t = red[tid];
#pragma unroll
        for (int o = 4; o > 0; o >>= 1) t += __shfl_xor_sync(0xffu, t, o);
        if (tid == 0) bc1 = t;
    }
    __syncthreads();
    const float rstd = rsqrtf(bc1 * (1.f / (float)DIM) + LN_EPS);

    yr[tid]       = d0 * rstd * gamma[tid]       + beta[tid];
    yr[tid + 256] = d1 * rstd * gamma[tid + 256] + beta[tid + 256];
    yr[tid + 512] = d2 * rstd * gamma[tid + 512] + beta[tid + 512];
}

// ---------------------------------------------------------------------------
// Launch
// ---------------------------------------------------------------------------
extern "C" void kernel_launch(void* const* d_in, const int* in_sizes, int n_in,
                              void* d_out, int out_size) {
    const int*   ids   = (const int*)  d_in[0];
    const float* adj_c = (const float*)d_in[1];
    const int*   gv_c  = (const int*)  d_in[2];
    const float* adj_h = (const float*)d_in[3];
    const int*   gv_h  = (const int*)  d_in[4];
    const float* adj_i = (const float*)d_in[5];
    const int*   gv_i  = (const int*)  d_in[6];
    const float* we    = (const float*)d_in[7];
    const float* pe    = (const float*)d_in[8];
    const float* W_c   = (const float*)d_in[9];
    const float* b_c   = (const float*)d_in[10];
    const float* W_h   = (const float*)d_in[11];
    const float* b_h   = (const float*)d_in[12];
    const float* W_i   = (const float*)d_in[13];
    const float* b_i   = (const float*)d_in[14];
    const float* Wp    = (const float*)d_in[15];
    const float* bp    = (const float*)d_in[16];
    const float* gam   = (const float*)d_in[17];
    const float* bet   = (const float*)d_in[18];
    float* Y = (float*)d_out;

    cudaFuncSetAttribute(proj_gemm_mma,
                         cudaFuncAttributeMaxDynamicSharedMemorySize, SMEM_DYN);

    emb_kernel<<<M_TOT, 192>>>(ids, we, pe);
    wpconv_kernel<<<DIM, 256>>>(Wp);
    colsum_kernel<<<dim3(BATCH, 3, 8), 512>>>(adj_c, adj_h, adj_i);
    pool_kernel<<<dim3(BATCH, 3, 4), 256>>>(gv_c, gv_h, gv_i, we);
    fc_kernel<<<dim3(BATCH, 3), 256>>>(W_c, b_c, W_h, b_h, W_i, b_i);
    bias2_kernel<<<BATCH, 256>>>(Wp, bp);
    proj_gemm_mma<<<dim3(DIM / 128, M_TOT / 128), 256, SMEM_DYN>>>(Y);
    ln_kernel<<<M_TOT, 256>>>(Y, gam, bet);
}

// round 11
// speedup vs baseline: 2.0984x; 1.0381x over previous
#include <cuda_runtime.h>
#include <cuda_bf16.h>
#include <cstdint>

#define BATCH 32
#define SEQ   512
#define DIM   768
#define GV    512
#define GD    16
#define M_TOT (BATCH * SEQ)          // 16384
#define WP_COLS (DIM + 3 * GD)       // 816
#define LN_EPS 1e-12f

// GEMM: C[16384,768] = A'[16384,2304] * B'[768,2304]^T  (bf16x3 split, mma.sync)
#define NKC 72                       // 2304 / 32 k-chunks
#define STAGE_BYTES 20480            // A 128x40 bf16 (10240) + B 128x40 bf16
#define SMEM_DYN (4 * STAGE_BYTES)   // 81920

// ---------------------------------------------------------------------------
// Device globals (scratch; no runtime allocation allowed)
// ---------------------------------------------------------------------------
__device__ __align__(16) __nv_bfloat16 g_emb_hi[(size_t)M_TOT * DIM];
__device__ __align__(16) __nv_bfloat16 g_emb_lo[(size_t)M_TOT * DIM];
__device__ __align__(16) __nv_bfloat16 g_wp_hi[DIM * DIM];
__device__ __align__(16) __nv_bfloat16 g_wp_lo[DIM * DIM];
__device__ __align__(16) float g_bias2[BATCH * DIM];
__device__ float g_graphvec[BATCH * 3 * GD];
__device__ float g_csum_part[BATCH * 3 * 8 * GV];
__device__ float g_pool[BATCH * 3 * 8 * DIM];

// ---------------------------------------------------------------------------
// PTX helpers (all base-sm_103 legal: cp.async, ldmatrix, mma.sync)
// ---------------------------------------------------------------------------
__device__ __forceinline__ uint32_t smem_u32(const void* p) {
    uint32_t a;
    asm("{ .reg .u64 t; cvta.to.shared.u64 t, %1; cvt.u32.u64 %0, t; }" : "=r"(a) : "l"(p));
    return a;
}
__device__ __forceinline__ void cp16(uint32_t dst, const void* src) {
    asm volatile("cp.async.cg.shared.global [%0], [%1], 16;" :: "r"(dst), "l"(src));
}
__device__ __forceinline__ void cp_commit() {
    asm volatile("cp.async.commit_group;" ::: "memory");
}
__device__ __forceinline__ void cp_wait2() {
    asm volatile("cp.async.wait_group 2;" ::: "memory");
}
__device__ __forceinline__ void ldm_x4(uint32_t& r0, uint32_t& r1, uint32_t& r2,
                                       uint32_t& r3, uint32_t addr) {
    asm volatile("ldmatrix.sync.aligned.m8n8.x4.shared.b16 {%0,%1,%2,%3}, [%4];"
                 : "=r"(r0), "=r"(r1), "=r"(r2), "=r"(r3) : "r"(addr));
}
__device__ __forceinline__ void mma16816(float* d, const uint32_t* a,
                                         uint32_t b0, uint32_t b1) {
    asm volatile(
        "mma.sync.aligned.m16n8k16.row.col.f32.bf16.bf16.f32 "
        "{%0,%1,%2,%3}, {%4,%5,%6,%7}, {%8,%9}, {%0,%1,%2,%3};"
        : "+f"(d[0]), "+f"(d[1]), "+f"(d[2]), "+f"(d[3])
        : "r"(a[0]), "r"(a[1]), "r"(a[2]), "r"(a[3]), "r"(b0), "r"(b1));
}

// stage load (128 threads): chunk c -> buffer (c&3). A/B 128 rows x 32 bf16, rows pad 80B
__device__ __forceinline__ void stage_load(uint32_t sb, int tid, int m0, int n0, int c) {
    const int st = c & 3;
    const int seg = c / 24;
    const int kk = (c - seg * 24) * 32;
    const char* As = (const char*)((seg == 1 ? g_emb_lo : g_emb_hi)
                                   + (size_t)m0 * DIM + kk);
    const char* Bs = (const char*)((seg == 2 ? g_wp_lo : g_wp_hi)
                                   + (size_t)n0 * DIM + kk);
    const uint32_t sa = sb + st * STAGE_BYTES;
    const uint32_t sbb = sa + 10240;
#pragma unroll
    for (int i = 0; i < 4; ++i) {
        const int ch = tid + i * 128;          // 0..511
        const int row = ch >> 2, c4 = ch & 3;  // row 0..127, 16B chunk 0..3
        cp16(sa + row * 80 + c4 * 16, As + (size_t)row * (DIM * 2) + c4 * 16);
        cp16(sbb + row * 80 + c4 * 16, Bs + (size_t)row * (DIM * 2) + c4 * 16);
    }
}

// ---------------------------------------------------------------------------
// K0: gather + pos add, split to bf16 hi/lo
// ---------------------------------------------------------------------------
__global__ void emb_kernel(const int* __restrict__ ids,
                           const float* __restrict__ we,
                           const float* __restrict__ pe) {
    const int m = blockIdx.x;
    const int t = threadIdx.x;               // 0..191
    const int id = ids[m];
    const int s = m & (SEQ - 1);
    float4 a = ((const float4*)(we + (size_t)id * DIM))[t];
    float4 p = ((const float4*)(pe + (size_t)s * DIM))[t];
    float v[4] = {a.x + p.x, a.y + p.y, a.z + p.z, a.w + p.w};
    __nv_bfloat16 h[4], l[4];
#pragma unroll
    for (int e = 0; e < 4; ++e) {
        h[e] = __float2bfloat16(v[e]);
        l[e] = __float2bfloat16(v[e] - __bfloat162float(h[e]));
    }
    const size_t off = (size_t)m * DIM + t * 4;
    *(uint2*)(g_emb_hi + off) = *(uint2*)h;
    *(uint2*)(g_emb_lo + off) = *(uint2*)l;
}

// ---------------------------------------------------------------------------
// K0b: W_proj[:, :768] -> bf16 hi/lo
// ---------------------------------------------------------------------------
__global__ void wpconv_kernel(const float* __restrict__ Wp) {
    const int n = blockIdx.x;
    const int tid = threadIdx.x;
#pragma unroll
    for (int i = 0; i < 3; ++i) {
        const int k = tid + i * 256;
        const float v = Wp[(size_t)n * WP_COLS + k];
        const __nv_bfloat16 h = __float2bfloat16(v);
        g_wp_hi[n * DIM + k] = h;
        g_wp_lo[n * DIM + k] = __float2bfloat16(v - __bfloat162float(h));
    }
}

// ---------------------------------------------------------------------------
// K1a: colsum partials over g-slices.  grid (32,3,8), 512 threads
// ---------------------------------------------------------------------------
__global__ void colsum_kernel(const float* __restrict__ adj_c,
                              const float* __restrict__ adj_h,
                              const float* __restrict__ adj_i) {
    const int b = blockIdx.x, br = blockIdx.y, z = blockIdx.z;
    const int tid = threadIdx.x;             // 0..511 = h
    const float* adj = (br == 0) ? adj_c : (br == 1) ? adj_h : adj_i;
    const float* adjb = adj + (size_t)b * GV * GV + (size_t)(z * 64) * GV;
    float a = 0.f;
#pragma unroll 4
    for (int g = 0; g < 64; ++g) a += adjb[(size_t)g * GV + tid];
    g_csum_part[(((b * 3) + br) * 8 + z) * GV + tid] = a;
}

// ---------------------------------------------------------------------------
// K1b: pool partials over 8 h-slices (64 h each).  grid (32,3,8), 256 threads
// ---------------------------------------------------------------------------
__global__ void pool_kernel(const int* __restrict__ gv_c,
                            const int* __restrict__ gv_h,
                            const int* __restrict__ gv_i,
                            const float* __restrict__ we) {
    __shared__ float cs[64];
    __shared__ int   gvs[64];
    const int b = blockIdx.x, br = blockIdx.y, w = blockIdx.z;
    const int tid = threadIdx.x;
    const int bb = b * 3 + br;
    const int hb = w * 64;
    const int* gv = (br == 0) ? gv_c : (br == 1) ? gv_h : gv_i;

    if (tid < 64) {
        float s = 0.f;
#pragma unroll
        for (int z = 0; z < 8; ++z)
            s += g_csum_part[(bb * 8 + z) * GV + hb + tid];
        cs[tid] = s;
        gvs[tid] = gv[b * GV + hb + tid];
    }
    __syncthreads();

    const int d0 = tid, d1 = tid + 256, d2 = tid + 512;
    float s0 = 0.f, s1 = 0.f, s2 = 0.f;
#pragma unroll 4
    for (int h = 0; h < 64; ++h) {
        const float wt = cs[h];
        const float* er = we + (size_t)gvs[h] * DIM;
        s0 += wt * er[d0];
        s1 += wt * er[d1];
        s2 += wt * er[d2];
    }
    float* out = g_pool + (size_t)(bb * 8 + w) * DIM;
    out[d0] = s0; out[d1] = s1; out[d2] = s2;
}

// ---------------------------------------------------------------------------
// K1c: reduce 8 pool partials + 16-wide FC + relu.  grid (32,3)
// ---------------------------------------------------------------------------
__global__ void fc_kernel(const float* __restrict__ W_c, const float* __restrict__ b_c,
                          const float* __restrict__ W_h, const float* __restrict__ b_h,
                          const float* __restrict__ W_i, const float* __restrict__ b_i) {
    __shared__ float gsh[DIM];
    const int b = blockIdx.x, br = blockIdx.y;
    const int tid = threadIdx.x;
    const int bb = b * 3 + br;
    const float* W; const float* bv;
    if (br == 0)      { W = W_c; bv = b_c; }
    else if (br == 1) { W = W_h; bv = b_h; }
    else              { W = W_i; bv = b_i; }

    const float* pool = g_pool + (size_t)bb * 8 * DIM;
#pragma unroll
    for (int i = 0; i < 3; ++i) {
        const int d = tid + i * 256;
        float s = 0.f;
#pragma unroll
        for (int p = 0; p < 8; ++p) s += pool[p * DIM + d];
        gsh[d] = s * (1.f / (float)GV);
    }
    __syncthreads();

    const int warp = tid >> 5, lane = tid & 31;
#pragma unroll
    for (int jj = 0; jj < 2; ++jj) {
        const int j = warp + jj * 8;
        float s = 0.f;
        for (int d = lane; d < DIM; d += 32) s += gsh[d] * W[j * DIM + d];
#pragma unroll
        for (int o = 16; o > 0; o >>= 1) s += __shfl_xor_sync(0xffffffffu, s, o);
        if (lane == 0)
            g_graphvec[b * 48 + br * GD + j] = fmaxf(s + bv[j], 0.f);
    }
}

// ---------------------------------------------------------------------------
// K2: bias2[b,d] = b_proj[d] + sum_{j<48} graphvec[b,j] * W_proj[d, 768+j]
// ---------------------------------------------------------------------------
__global__ void bias2_kernel(const float* __restrict__ Wp,
                             const float* __restrict__ bp) {
    __shared__ float gvs[48];
    const int b = blockIdx.x;
    const int tid = threadIdx.x;
    if (tid < 48) gvs[tid] = g_graphvec[b * 48 + tid];
    __syncthreads();
    for (int d = tid; d < DIM; d += 256) {
        float s = bp[d];
        const float* wr = Wp + (size_t)d * WP_COLS + DIM;
#pragma unroll
        for (int j = 0; j < 48; ++j) s += gvs[j] * wr[j];
        g_bias2[b * DIM + d] = s;
    }
}

// ---------------------------------------------------------------------------
// K3: bf16x3 GEMM via mma.sync.  CTA 128x128, 4 warps x (64x64), 4-stage cp.async
// ---------------------------------------------------------------------------
__global__ __launch_bounds__(128, 2)
void proj_gemm_mma(float* __restrict__ Y) {
    extern __shared__ char smem[];
    const uint32_t sb = smem_u32(smem);
    const int tid = threadIdx.x;
    const int wid = tid >> 5, lane = tid & 31;
    const int m0 = blockIdx.y * 128;
    const int n0 = blockIdx.x * 128;
    const int wm = wid & 1;          // M half (64 rows)
    const int wn = wid >> 1;         // N half (64 cols)

    float acc[4][8][4];
#pragma unroll
    for (int i = 0; i < 4; ++i)
#pragma unroll
        for (int j = 0; j < 8; ++j)
#pragma unroll
            for (int e = 0; e < 4; ++e) acc[i][j][e] = 0.f;

    // prologue: prefetch 3 stages
    stage_load(sb, tid, m0, n0, 0); cp_commit();
    stage_load(sb, tid, m0, n0, 1); cp_commit();
    stage_load(sb, tid, m0, n0, 2); cp_commit();

    const int lrow = lane & 15, lhal = (lane >> 4) << 4;  // ldmatrix addr pieces

    for (int c = 0; c < NKC; ++c) {
        cp_wait2();
        __syncthreads();
        // issue next-stage loads first (buffer (c+3)&3 == (c-1)&3; its readers —
        // chunk c-1's mma — are provably done past the barrier above)
        if (c + 3 < NKC) stage_load(sb, tid, m0, n0, c + 3);
        cp_commit();                       // empty group on tail keeps wait uniform
        const uint32_t sa = sb + (c & 3) * STAGE_BYTES;
        const uint32_t sbb = sa + 10240;
#pragma unroll
        for (int ks = 0; ks < 2; ++ks) {
            uint32_t a[4][4];
            uint32_t bfr[8][2];
#pragma unroll
            for (int i = 0; i < 4; ++i)
                ldm_x4(a[i][0], a[i][1], a[i][2], a[i][3],
                       sa + (uint32_t)(wm * 64 + i * 16 + lrow) * 80 + ks * 32 + lhal);
#pragma unroll
            for (int j = 0; j < 4; ++j) {
                uint32_t r0, r1, r2, r3;
                ldm_x4(r0, r1, r2, r3,
                       sbb + (uint32_t)(wn * 64 + j * 16 + lrow) * 80 + ks * 32 + lhal);
                bfr[j * 2 + 0][0] = r0; bfr[j * 2 + 1][0] = r1;
                bfr[j * 2 + 0][1] = r2; bfr[j * 2 + 1][1] = r3;
            }
#pragma unroll
            for (int i = 0; i < 4; ++i)
#pragma unroll
                for (int nt = 0; nt < 8; ++nt)
                    mma16816(acc[i][nt], a[i], bfr[nt][0], bfr[nt][1]);
        }
    }

    // epilogue: direct stores + bias2
    const int bidx = m0 >> 9;
    const float* bz = g_bias2 + bidx * DIM + n0 + wn * 64;
    float* ybase = Y + (size_t)(m0 + wm * 64) * DIM + n0 + wn * 64;
#pragma unroll
    for (int nt = 0; nt < 8; ++nt) {
        const int n = nt * 8 + (lane & 3) * 2;
        const float2 bv = *(const float2*)(bz + n);
#pragma unroll
        for (int i = 0; i < 4; ++i) {
            const int r = i * 16 + (lane >> 2);
            float2 o0 = make_float2(acc[i][nt][0] + bv.x, acc[i][nt][1] + bv.y);
            float2 o1 = make_float2(acc[i][nt][2] + bv.x, acc[i][nt][3] + bv.y);
            *(float2*)(ybase + (size_t)r * DIM + n) = o0;
            *(float2*)(ybase + (size_t)(r + 8) * DIM + n) = o1;
        }
    }
}

// ---------------------------------------------------------------------------
// K4: in-place LayerNorm over last dim (768)
// ---------------------------------------------------------------------------
__global__ void ln_kernel(float* __restrict__ Y,
                          const float* __restrict__ gamma,
                          const float* __restrict__ beta) {
    __shared__ float red[8];
    __shared__ float bc0, bc1;
    const int row = blockIdx.x;
    const int tid = threadIdx.x;
    float* yr = Y + (size_t)row * DIM;
    const float v0 = yr[tid], v1 = yr[tid + 256], v2 = yr[tid + 512];

    float s = v0 + v1 + v2;
#pragma unroll
    for (int o = 16; o > 0; o >>= 1) s += __shfl_xor_sync(0xffffffffu, s, o);
    if ((tid & 31) == 0) red[tid >> 5] = s;
    __syncthreads();
    if (tid < 8) {
        float t = red[tid];
#pragma unroll
        for (int o = 4; o > 0; o >>= 1) t += __shfl_xor_sync(0xffu, t, o);
        if (tid == 0) bc0 = t;
    }
    __syncthreads();
    const float mu = bc0 * (1.f / (float)DIM);
    const float d0 = v0 - mu, d1 = v1 - mu, d2 = v2 - mu;

    float q = d0 * d0 + d1 * d1 + d2 * d2;
#pragma unroll
    for (int o = 16; o > 0; o >>= 1) q += __shfl_xor_sync(0xffffffffu, q, o);
    __syncthreads();
    if ((tid & 31) == 0) red[tid >> 5] = q;
    __syncthreads();
    if (tid < 8) {
        float t = red[tid];
#pragma unroll
        for (int o = 4; o > 0; o >>= 1) t += __shfl_xor_sync(0xffu, t, o);
        if (tid == 0) bc1 = t;
    }
    __syncthreads();
    const float rstd = rsqrtf(bc1 * (1.f / (float)DIM) + LN_EPS);

    yr[tid]       = d0 * rstd * gamma[tid]       + beta[tid];
    yr[tid + 256] = d1 * rstd * gamma[tid + 256] + beta[tid + 256];
    yr[tid + 512] = d2 * rstd * gamma[tid + 512] + beta[tid + 512];
}

// ---------------------------------------------------------------------------
// Launch
// ---------------------------------------------------------------------------
extern "C" void kernel_launch(void* const* d_in, const int* in_sizes, int n_in,
                              void* d_out, int out_size) {
    const int*   ids   = (const int*)  d_in[0];
    const float* adj_c = (const float*)d_in[1];
    const int*   gv_c  = (const int*)  d_in[2];
    const float* adj_h = (const float*)d_in[3];
    const int*   gv_h  = (const int*)  d_in[4];
    const float* adj_i = (const float*)d_in[5];
    const int*   gv_i  = (const int*)  d_in[6];
    const float* we    = (const float*)d_in[7];
    const float* pe    = (const float*)d_in[8];
    const float* W_c   = (const float*)d_in[9];
    const float* b_c   = (const float*)d_in[10];
    const float* W_h   = (const float*)d_in[11];
    const float* b_h   = (const float*)d_in[12];
    const float* W_i   = (const float*)d_in[13];
    const float* b_i   = (const float*)d_in[14];
    const float* Wp    = (const float*)d_in[15];
    const float* bp    = (const float*)d_in[16];
    const float* gam   = (const float*)d_in[17];
    const float* bet   = (const float*)d_in[18];
    float* Y = (float*)d_out;

    cudaFuncSetAttribute(proj_gemm_mma,
                         cudaFuncAttributeMaxDynamicSharedMemorySize, SMEM_DYN);

    emb_kernel<<<M_TOT, 192>>>(ids, we, pe);
    wpconv_kernel<<<DIM, 256>>>(Wp);
    colsum_kernel<<<dim3(BATCH, 3, 8), 512>>>(adj_c, adj_h, adj_i);
    pool_kernel<<<dim3(BATCH, 3, 8), 256>>>(gv_c, gv_h, gv_i, we);
    fc_kernel<<<dim3(BATCH, 3), 256>>>(W_c, b_c, W_h, b_h, W_i, b_i);
    bias2_kernel<<<BATCH, 256>>>(Wp, bp);
    proj_gemm_mma<<<dim3(DIM / 128, M_TOT / 128), 128, SMEM_DYN>>>(Y);
    ln_kernel<<<M_TOT, 256>>>(Y, gam, bet);
}

// round 14
// speedup vs baseline: 2.3278x; 1.1093x over previous
#include <cuda_runtime.h>
#include <cuda_bf16.h>
#include <cstdint>

#define BATCH 32
#define SEQ   512
#define DIM   768
#define GV    512
#define GD    16
#define M_TOT (BATCH * SEQ)          // 16384
#define WP_COLS (DIM + 3 * GD)       // 816
#define LN_EPS 1e-12f

// GEMM: C[16384,768] = A'[16384,2304] * B'[768,2304]^T  (bf16x3 split, mma.sync)
#define NKC 72                       // 2304 / 32 k-chunks
#define STAGE_BYTES 20480            // A 128x40 bf16 (10240) + B 128x40 bf16
#define SMEM_DYN (4 * STAGE_BYTES)   // 81920

// ---------------------------------------------------------------------------
// Device globals (scratch; no runtime allocation allowed)
// ---------------------------------------------------------------------------
__device__ __align__(16) __nv_bfloat16 g_emb_hi[(size_t)M_TOT * DIM];
__device__ __align__(16) __nv_bfloat16 g_emb_lo[(size_t)M_TOT * DIM];
__device__ __align__(16) __nv_bfloat16 g_wp_hi[DIM * DIM];
__device__ __align__(16) __nv_bfloat16 g_wp_lo[DIM * DIM];
__device__ __align__(16) float g_bias2[BATCH * DIM];
__device__ float g_graphvec[BATCH * 3 * GD];
__device__ float g_csum_part[BATCH * 3 * 8 * GV];
__device__ float g_pool[BATCH * 3 * 8 * DIM];

// ---------------------------------------------------------------------------
// PTX helpers (all base-sm_103 legal: cp.async, ldmatrix, mma.sync)
// ---------------------------------------------------------------------------
__device__ __forceinline__ uint32_t smem_u32(const void* p) {
    uint32_t a;
    asm("{ .reg .u64 t; cvta.to.shared.u64 t, %1; cvt.u32.u64 %0, t; }" : "=r"(a) : "l"(p));
    return a;
}
__device__ __forceinline__ void cp16(uint32_t dst, const void* src) {
    asm volatile("cp.async.cg.shared.global [%0], [%1], 16;" :: "r"(dst), "l"(src));
}
__device__ __forceinline__ void cp_commit() {
    asm volatile("cp.async.commit_group;" ::: "memory");
}
__device__ __forceinline__ void cp_wait2() {
    asm volatile("cp.async.wait_group 2;" ::: "memory");
}
__device__ __forceinline__ void ldm_x4(uint32_t& r0, uint32_t& r1, uint32_t& r2,
                                       uint32_t& r3, uint32_t addr) {
    asm volatile("ldmatrix.sync.aligned.m8n8.x4.shared.b16 {%0,%1,%2,%3}, [%4];"
                 : "=r"(r0), "=r"(r1), "=r"(r2), "=r"(r3) : "r"(addr));
}
__device__ __forceinline__ void mma16816(float* d, const uint32_t* a,
                                         uint32_t b0, uint32_t b1) {
    asm volatile(
        "mma.sync.aligned.m16n8k16.row.col.f32.bf16.bf16.f32 "
        "{%0,%1,%2,%3}, {%4,%5,%6,%7}, {%8,%9}, {%0,%1,%2,%3};"
        : "+f"(d[0]), "+f"(d[1]), "+f"(d[2]), "+f"(d[3])
        : "r"(a[0]), "r"(a[1]), "r"(a[2]), "r"(a[3]), "r"(b0), "r"(b1));
}

// stage load (128 threads): chunk c -> buffer (c&3). A/B 128 rows x 32 bf16, rows pad 80B
__device__ __forceinline__ void stage_load(uint32_t sb, int tid, int m0, int n0, int c) {
    const int st = c & 3;
    const int seg = c / 24;
    const int kk = (c - seg * 24) * 32;
    const char* As = (const char*)((seg == 1 ? g_emb_lo : g_emb_hi)
                                   + (size_t)m0 * DIM + kk);
    const char* Bs = (const char*)((seg == 2 ? g_wp_lo : g_wp_hi)
                                   + (size_t)n0 * DIM + kk);
    const uint32_t sa = sb + st * STAGE_BYTES;
    const uint32_t sbb = sa + 10240;
#pragma unroll
    for (int i = 0; i < 4; ++i) {
        const int ch = tid + i * 128;          // 0..511
        const int row = ch >> 2, c4 = ch & 3;  // row 0..127, 16B chunk 0..3
        cp16(sa + row * 80 + c4 * 16, As + (size_t)row * (DIM * 2) + c4 * 16);
        cp16(sbb + row * 80 + c4 * 16, Bs + (size_t)row * (DIM * 2) + c4 * 16);
    }
}

// ---------------------------------------------------------------------------
// K0: gather + pos add, split to bf16 hi/lo
// ---------------------------------------------------------------------------
__global__ void emb_kernel(const int* __restrict__ ids,
                           const float* __restrict__ we,
                           const float* __restrict__ pe) {
    const int m = blockIdx.x;
    const int t = threadIdx.x;               // 0..191
    const int id = ids[m];
    const int s = m & (SEQ - 1);
    float4 a = ((const float4*)(we + (size_t)id * DIM))[t];
    float4 p = ((const float4*)(pe + (size_t)s * DIM))[t];
    float v[4] = {a.x + p.x, a.y + p.y, a.z + p.z, a.w + p.w};
    __nv_bfloat16 h[4], l[4];
#pragma unroll
    for (int e = 0; e < 4; ++e) {
        h[e] = __float2bfloat16(v[e]);
        l[e] = __float2bfloat16(v[e] - __bfloat162float(h[e]));
    }
    const size_t off = (size_t)m * DIM + t * 4;
    *(uint2*)(g_emb_hi + off) = *(uint2*)h;
    *(uint2*)(g_emb_lo + off) = *(uint2*)l;
}

// ---------------------------------------------------------------------------
// K0b: W_proj[:, :768] -> bf16 hi/lo
// ---------------------------------------------------------------------------
__global__ void wpconv_kernel(const float* __restrict__ Wp) {
    const int n = blockIdx.x;
    const int tid = threadIdx.x;
#pragma unroll
    for (int i = 0; i < 3; ++i) {
        const int k = tid + i * 256;
        const float v = Wp[(size_t)n * WP_COLS + k];
        const __nv_bfloat16 h = __float2bfloat16(v);
        g_wp_hi[n * DIM + k] = h;
        g_wp_lo[n * DIM + k] = __float2bfloat16(v - __bfloat162float(h));
    }
}

// ---------------------------------------------------------------------------
// K1a: colsum partials over g-slices.  grid (32,3,8), 512 threads
// ---------------------------------------------------------------------------
__global__ void colsum_kernel(const float* __restrict__ adj_c,
                              const float* __restrict__ adj_h,
                              const float* __restrict__ adj_i) {
    const int b = blockIdx.x, br = blockIdx.y, z = blockIdx.z;
    const int tid = threadIdx.x;             // 0..511 = h
    const float* adj = (br == 0) ? adj_c : (br == 1) ? adj_h : adj_i;
    const float* adjb = adj + (size_t)b * GV * GV + (size_t)(z * 64) * GV;
    float a = 0.f;
#pragma unroll 4
    for (int g = 0; g < 64; ++g) a += adjb[(size_t)g * GV + tid];
    g_csum_part[(((b * 3) + br) * 8 + z) * GV + tid] = a;
}

// ---------------------------------------------------------------------------
// K1b: pool partials over 8 h-slices (64 h each).  grid (32,3,8), 256 threads
// ---------------------------------------------------------------------------
__global__ void pool_kernel(const int* __restrict__ gv_c,
                            const int* __restrict__ gv_h,
                            const int* __restrict__ gv_i,
                            const float* __restrict__ we) {
    __shared__ float cs[64];
    __shared__ int   gvs[64];
    const int b = blockIdx.x, br = blockIdx.y, w = blockIdx.z;
    const int tid = threadIdx.x;
    const int bb = b * 3 + br;
    const int hb = w * 64;
    const int* gv = (br == 0) ? gv_c : (br == 1) ? gv_h : gv_i;

    if (tid < 64) {
        float s = 0.f;
#pragma unroll
        for (int z = 0; z < 8; ++z)
            s += g_csum_part[(bb * 8 + z) * GV + hb + tid];
        cs[tid] = s;
        gvs[tid] = gv[b * GV + hb + tid];
    }
    __syncthreads();

    const int d0 = tid, d1 = tid + 256, d2 = tid + 512;
    float s0 = 0.f, s1 = 0.f, s2 = 0.f;
#pragma unroll 4
    for (int h = 0; h < 64; ++h) {
        const float wt = cs[h];
        const float* er = we + (size_t)gvs[h] * DIM;
        s0 += wt * er[d0];
        s1 += wt * er[d1];
        s2 += wt * er[d2];
    }
    float* out = g_pool + (size_t)(bb * 8 + w) * DIM;
    out[d0] = s0; out[d1] = s1; out[d2] = s2;
}

// ---------------------------------------------------------------------------
// K1c: reduce 8 pool partials + 16-wide FC + relu.  grid (32,3)
// ---------------------------------------------------------------------------
__global__ void fc_kernel(const float* __restrict__ W_c, const float* __restrict__ b_c,
                          const float* __restrict__ W_h, const float* __restrict__ b_h,
                          const float* __restrict__ W_i, const float* __restrict__ b_i) {
    __shared__ float gsh[DIM];
    const int b = blockIdx.x, br = blockIdx.y;
    const int tid = threadIdx.x;
    const int bb = b * 3 + br;
    const float* W; const float* bv;
    if (br == 0)      { W = W_c; bv = b_c; }
    else if (br == 1) { W = W_h; bv = b_h; }
    else              { W = W_i; bv = b_i; }

    const float* pool = g_pool + (size_t)bb * 8 * DIM;
#pragma unroll
    for (int i = 0; i < 3; ++i) {
        const int d = tid + i * 256;
        float s = 0.f;
#pragma unroll
        for (int p = 0; p < 8; ++p) s += pool[p * DIM + d];
        gsh[d] = s * (1.f / (float)GV);
    }
    __syncthreads();

    const int warp = tid >> 5, lane = tid & 31;
#pragma unroll
    for (int jj = 0; jj < 2; ++jj) {
        const int j = warp + jj * 8;
        float s = 0.f;
        for (int d = lane; d < DIM; d += 32) s += gsh[d] * W[j * DIM + d];
#pragma unroll
        for (int o = 16; o > 0; o >>= 1) s += __shfl_xor_sync(0xffffffffu, s, o);
        if (lane == 0)
            g_graphvec[b * 48 + br * GD + j] = fmaxf(s + bv[j], 0.f);
    }
}

// ---------------------------------------------------------------------------
// K2: bias2[b,d] = b_proj[d] + sum_{j<48} graphvec[b,j] * W_proj[d, 768+j]
// ---------------------------------------------------------------------------
__global__ void bias2_kernel(const float* __restrict__ Wp,
                             const float* __restrict__ bp) {
    __shared__ float gvs[48];
    const int b = blockIdx.x;
    const int tid = threadIdx.x;
    if (tid < 48) gvs[tid] = g_graphvec[b * 48 + tid];
    __syncthreads();
    for (int d = tid; d < DIM; d += 256) {
        float s = bp[d];
        const float* wr = Wp + (size_t)d * WP_COLS + DIM;
#pragma unroll
        for (int j = 0; j < 48; ++j) s += gvs[j] * wr[j];
        g_bias2[b * DIM + d] = s;
    }
}

// ---------------------------------------------------------------------------
// K3: bf16x3 GEMM via mma.sync.  CTA 128x128, 4 warps x (64x64), 4-stage cp.async
// (bias2 NOT added here — folded into ln_kernel so the GEMM doesn't depend on
//  the VGCN side-stream chain)
// ---------------------------------------------------------------------------
__global__ __launch_bounds__(128, 2)
void proj_gemm_mma(float* __restrict__ Y) {
    extern __shared__ char smem[];
    const uint32_t sb = smem_u32(smem);
    const int tid = threadIdx.x;
    const int wid = tid >> 5, lane = tid & 31;
    const int m0 = blockIdx.y * 128;
    const int n0 = blockIdx.x * 128;
    const int wm = wid & 1;          // M half (64 rows)
    const int wn = wid >> 1;         // N half (64 cols)

    float acc[4][8][4];
#pragma unroll
    for (int i = 0; i < 4; ++i)
#pragma unroll
        for (int j = 0; j < 8; ++j)
#pragma unroll
            for (int e = 0; e < 4; ++e) acc[i][j][e] = 0.f;

    // prologue: prefetch 3 stages
    stage_load(sb, tid, m0, n0, 0); cp_commit();
    stage_load(sb, tid, m0, n0, 1); cp_commit();
    stage_load(sb, tid, m0, n0, 2); cp_commit();

    const int lrow = lane & 15, lhal = (lane >> 4) << 4;  // ldmatrix addr pieces

    for (int c = 0; c < NKC; ++c) {
        cp_wait2();
        __syncthreads();
        // issue next-stage loads first (buffer (c+3)&3 == (c-1)&3; its readers —
        // chunk c-1's mma — are provably done past the barrier above)
        if (c + 3 < NKC) stage_load(sb, tid, m0, n0, c + 3);
        cp_commit();                       // empty group on tail keeps wait uniform
        const uint32_t sa = sb + (c & 3) * STAGE_BYTES;
        const uint32_t sbb = sa + 10240;
#pragma unroll
        for (int ks = 0; ks < 2; ++ks) {
            uint32_t a[4][4];
            uint32_t bfr[8][2];
#pragma unroll
            for (int i = 0; i < 4; ++i)
                ldm_x4(a[i][0], a[i][1], a[i][2], a[i][3],
                       sa + (uint32_t)(wm * 64 + i * 16 + lrow) * 80 + ks * 32 + lhal);
#pragma unroll
            for (int j = 0; j < 4; ++j) {
                uint32_t r0, r1, r2, r3;
                ldm_x4(r0, r1, r2, r3,
                       sbb + (uint32_t)(wn * 64 + j * 16 + lrow) * 80 + ks * 32 + lhal);
                bfr[j * 2 + 0][0] = r0; bfr[j * 2 + 1][0] = r1;
                bfr[j * 2 + 0][1] = r2; bfr[j * 2 + 1][1] = r3;
            }
#pragma unroll
            for (int i = 0; i < 4; ++i)
#pragma unroll
                for (int nt = 0; nt < 8; ++nt)
                    mma16816(acc[i][nt], a[i], bfr[nt][0], bfr[nt][1]);
        }
    }

    // epilogue: direct stores (raw accumulators)
    float* ybase = Y + (size_t)(m0 + wm * 64) * DIM + n0 + wn * 64;
#pragma unroll
    for (int nt = 0; nt < 8; ++nt) {
        const int n = nt * 8 + (lane & 3) * 2;
#pragma unroll
        for (int i = 0; i < 4; ++i) {
            const int r = i * 16 + (lane >> 2);
            *(float2*)(ybase + (size_t)r * DIM + n) =
                make_float2(acc[i][nt][0], acc[i][nt][1]);
            *(float2*)(ybase + (size_t)(r + 8) * DIM + n) =
                make_float2(acc[i][nt][2], acc[i][nt][3]);
        }
    }
}

// ---------------------------------------------------------------------------
// K4: in-place bias2-add + LayerNorm over last dim (768)
// ---------------------------------------------------------------------------
__global__ void ln_kernel(float* __restrict__ Y,
                          const float* __restrict__ gamma,
                          const float* __restrict__ beta) {
    __shared__ float red[8];
    __shared__ float bc0, bc1;
    const int row = blockIdx.x;
    const int tid = threadIdx.x;
    float* yr = Y + (size_t)row * DIM;
    const float* bz = g_bias2 + (size_t)(row >> 9) * DIM;
    const float v0 = yr[tid] + bz[tid];
    const float v1 = yr[tid + 256] + bz[tid + 256];
    const float v2 = yr[tid + 512] + bz[tid + 512];

    float s = v0 + v1 + v2;
#pragma unroll
    for (int o = 16; o > 0; o >>= 1) s += __shfl_xor_sync(0xffffffffu, s, o);
    if ((tid & 31) == 0) red[tid >> 5] = s;
    __syncthreads();
    if (tid < 8) {
        float t = red[tid];
#pragma unroll
        for (int o = 4; o > 0; o >>= 1) t += __shfl_xor_sync(0xffu, t, o);
        if (tid == 0) bc0 = t;
    }
    __syncthreads();
    const float mu = bc0 * (1.f / (float)DIM);
    const float d0 = v0 - mu, d1 = v1 - mu, d2 = v2 - mu;

    float q = d0 * d0 + d1 * d1 + d2 * d2;
#pragma unroll
    for (int o = 16; o > 0; o >>= 1) q += __shfl_xor_sync(0xffffffffu, q, o);
    __syncthreads();
    if ((tid & 31) == 0) red[tid >> 5] = q;
    __syncthreads();
    if (tid < 8) {
        float t = red[tid];
#pragma unroll
        for (int o = 4; o > 0; o >>= 1) t += __shfl_xor_sync(0xffu, t, o);
        if (tid == 0) bc1 = t;
    }
    __syncthreads();
    const float rstd = rsqrtf(bc1 * (1.f / (float)DIM) + LN_EPS);

    yr[tid]       = d0 * rstd * gamma[tid]       + beta[tid];
    yr[tid + 256] = d1 * rstd * gamma[tid + 256] + beta[tid + 256];
    yr[tid + 512] = d2 * rstd * gamma[tid + 512] + beta[tid + 512];
}

// ---------------------------------------------------------------------------
// Launch: GEMM path on main stream, VGCN chain forked onto a non-blocking
// side stream (fork/join via events — standard capturable pattern).
// Stream/events are created once, on the first (non-captured) correctness call.
// ---------------------------------------------------------------------------
extern "C" void kernel_launch(void* const* d_in, const int* in_sizes, int n_in,
                              void* d_out, int out_size) {
    const int*   ids   = (const int*)  d_in[0];
    const float* adj_c = (const float*)d_in[1];
    const int*   gv_c  = (const int*)  d_in[2];
    const float* adj_h = (const float*)d_in[3];
    const int*   gv_h  = (const int*)  d_in[4];
    const float* adj_i = (const float*)d_in[5];
    const int*   gv_i  = (const int*)  d_in[6];
    const float* we    = (const float*)d_in[7];
    const float* pe    = (const float*)d_in[8];
    const float* W_c   = (const float*)d_in[9];
    const float* b_c   = (const float*)d_in[10];
    const float* W_h   = (const float*)d_in[11];
    const float* b_h   = (const float*)d_in[12];
    const float* W_i   = (const float*)d_in[13];
    const float* b_i   = (const float*)d_in[14];
    const float* Wp    = (const float*)d_in[15];
    const float* bp    = (const float*)d_in[16];
    const float* gam   = (const float*)d_in[17];
    const float* bet   = (const float*)d_in[18];
    float* Y = (float*)d_out;

    static cudaStream_t s_side = nullptr;
    static cudaEvent_t s_fork = nullptr, s_join = nullptr;
    static bool s_attr_done = false;
    if (!s_side) {
        cudaStreamCreateWithFlags(&s_side, cudaStreamNonBlocking);
        cudaEventCreateWithFlags(&s_fork, cudaEventDisableTiming);
        cudaEventCreateWithFlags(&s_join, cudaEventDisableTiming);
    }
    if (!s_attr_done) {
        cudaFuncSetAttribute(proj_gemm_mma,
                             cudaFuncAttributeMaxDynamicSharedMemorySize, SMEM_DYN);
        s_attr_done = true;
    }

    // fork: VGCN chain on side stream (independent of emb/wpconv/GEMM)
    cudaEventRecord(s_fork, 0);
    cudaStreamWaitEvent(s_side, s_fork, 0);
    colsum_kernel<<<dim3(BATCH, 3, 8), 512, 0, s_side>>>(adj_c, adj_h, adj_i);
    pool_kernel<<<dim3(BATCH, 3, 8), 256, 0, s_side>>>(gv_c, gv_h, gv_i, we);
    fc_kernel<<<dim3(BATCH, 3), 256, 0, s_side>>>(W_c, b_c, W_h, b_h, W_i, b_i);
    bias2_kernel<<<BATCH, 256, 0, s_side>>>(Wp, bp);
    cudaEventRecord(s_join, s_side);

    // main stream: embedding prep + GEMM (tensor-pipe-bound; overlaps side chain)
    emb_kernel<<<M_TOT, 192>>>(ids, we, pe);
    wpconv_kernel<<<DIM, 256>>>(Wp);
    proj_gemm_mma<<<dim3(DIM / 128, M_TOT / 128), 128, SMEM_DYN>>>(Y);

    // join: ln needs bias2 (side) + Y (main)
    cudaStreamWaitEvent(0, s_join, 0);
    ln_kernel<<<M_TOT, 256>>>(Y, gam, bet);
}